// round 11
// baseline (speedup 1.0000x reference)
#include <cuda_runtime.h>
#include <cuda_fp16.h>

#define N_NODES 100000
#define N_EDGES 1600000
#define IN_CH   32
#define HID     128
#define OUT_CH  32
#define SCAN_B  1024
#define N_SBLK  ((N_NODES + SCAN_B - 1) / SCAN_B)   // 98

// prep_kernel block ranges
#define PB_XHALF 3125              // 3125*512 = 1.6M half2
#define PB_W1    (PB_XHALF + 32)
#define PB_W2    (PB_W1 + 32)
#define PB_TOT   (PB_W2 + 1)       // +1 detect/state block

// ---------------- scratch (device globals; no allocation allowed) ----------
__device__ __align__(16) int    g_cnt[N_NODES];           // zero-recycled each call
__device__ __align__(16) int    g_off[N_NODES + 1];
__device__ __align__(16) int    g_cur[N_NODES];
__device__ __align__(16) int    g_col[N_EDGES];
__device__ __align__(16) float  g_inv[N_NODES];
__device__ __align__(8)  unsigned long long g_state[N_SBLK]; // lookback state
__device__ __align__(16) __half2 g_xh2[N_NODES * 16];     // x fp16, 64B rows
__device__ __align__(16) float  g_agg1[N_NODES * IN_CH];  // fp32 sum, L1
__device__ __align__(16) __half g_hf[N_NODES * HID];      // relu(L1) fp16
__device__ __align__(16) __half g_pf[N_NODES * OUT_CH];   // p = h @ W2l^T fp16
__device__ __align__(16) __half g_w1h[128 * 64];          // [W1l | W1r] fp16
__device__ __align__(16) __half g_w2h[32 * 256];          // [W2l | W2r] fp16
__device__ int g_is64;

static __device__ __forceinline__ unsigned smem_u32(const void* p) {
    unsigned r;
    asm("{ .reg .u64 t; cvta.to.shared.u64 t, %1; cvt.u32.u64 %0, t; }"
        : "=r"(r) : "l"(p));
    return r;
}
static __device__ __forceinline__ unsigned long long ld_acq(unsigned long long* p) {
    unsigned long long v;
    asm volatile("ld.acquire.gpu.u64 %0, [%1];" : "=l"(v) : "l"(p) : "memory");
    return v;
}
static __device__ __forceinline__ void st_rel(unsigned long long* p, unsigned long long v) {
    asm volatile("st.release.gpu.u64 [%0], %1;" :: "l"(p), "l"(v) : "memory");
}

#define LDMATRIX_X4(a0,a1,a2,a3,addr) \
    asm volatile("ldmatrix.sync.aligned.m8n8.x4.shared.b16 {%0,%1,%2,%3}, [%4];" \
        : "=r"(a0),"=r"(a1),"=r"(a2),"=r"(a3) : "r"(addr))
#define LDMATRIX_X2(b0,b1,addr) \
    asm volatile("ldmatrix.sync.aligned.m8n8.x2.shared.b16 {%0,%1}, [%2];" \
        : "=r"(b0),"=r"(b1) : "r"(addr))
#define MMA16816(d,a0,a1,a2,a3,b0,b1) \
    asm volatile("mma.sync.aligned.m16n8k16.row.col.f32.f16.f16.f32 " \
        "{%0,%1,%2,%3}, {%4,%5,%6,%7}, {%8,%9}, {%0,%1,%2,%3};" \
        : "+f"(d[0]),"+f"(d[1]),"+f"(d[2]),"+f"(d[3]) \
        : "r"(a0),"r"(a1),"r"(a2),"r"(a3),"r"(b0),"r"(b1))

// ---------------- prep: xhalf + wconv1 + wconv2 + detect + state reset -----
__global__ void prep_kernel(const float* __restrict__ x,
                            const float* __restrict__ W1l,
                            const float* __restrict__ W1r,
                            const float* __restrict__ W2l,
                            const float* __restrict__ W2r,
                            const unsigned int* __restrict__ ei32) {
    int b = blockIdx.x, tid = threadIdx.x;
    if (b < PB_XHALF) {
        int i = b * 512 + tid;
        float2 v0 = ((const float2*)x)[i];
        g_xh2[i] = __floats2half2_rn(v0.x, v0.y);
        int i2 = i + 256;
        float2 v1 = ((const float2*)x)[i2];
        g_xh2[i2] = __floats2half2_rn(v1.x, v1.y);
    } else if (b < PB_W1) {
        int i = (b - PB_XHALF) * 256 + tid;     // 8192 = 128*64
        int row = i >> 6, k = i & 63;
        float v = (k < 32) ? W1l[row * 32 + k] : W1r[row * 32 + (k - 32)];
        g_w1h[i] = __float2half_rn(v);
    } else if (b < PB_W2) {
        int i = (b - PB_W1) * 256 + tid;        // 8192 = 32*256
        int row = i >> 8, k = i & 255;
        float v = (k < 128) ? W2l[row * 128 + k] : W2r[row * 128 + (k - 128)];
        g_w2h[i] = __float2half_rn(v);
    } else {
        __shared__ int flag;
        if (tid == 0) flag = 0;
        if (tid < N_SBLK) g_state[tid] = 0ull;  // reset lookback state
        __syncthreads();
        if (tid < 128 && ei32[2 * tid + 1] != 0u) flag = 1;
        __syncthreads();
        if (tid == 0) g_is64 = flag ? 0 : 1;
    }
}

// ---------------- hist (8 edges per thread, batched loads) -----------------
__global__ void hist_kernel(const void* ei) {
    int t = blockIdx.x * blockDim.x + threadIdx.x;
    if (t >= N_EDGES / 8) return;
    if (g_is64) {
        const longlong2* dp = (const longlong2*)((const long long*)ei + N_EDGES);
        longlong2 d0 = dp[t * 4], d1 = dp[t * 4 + 1];
        longlong2 d2 = dp[t * 4 + 2], d3 = dp[t * 4 + 3];
        atomicAdd(&g_cnt[(int)d0.x], 1); atomicAdd(&g_cnt[(int)d0.y], 1);
        atomicAdd(&g_cnt[(int)d1.x], 1); atomicAdd(&g_cnt[(int)d1.y], 1);
        atomicAdd(&g_cnt[(int)d2.x], 1); atomicAdd(&g_cnt[(int)d2.y], 1);
        atomicAdd(&g_cnt[(int)d3.x], 1); atomicAdd(&g_cnt[(int)d3.y], 1);
    } else {
        const int4* dp = (const int4*)((const int*)ei + N_EDGES);
        int4 d0 = dp[t * 2], d1 = dp[t * 2 + 1];
        atomicAdd(&g_cnt[d0.x], 1); atomicAdd(&g_cnt[d0.y], 1);
        atomicAdd(&g_cnt[d0.z], 1); atomicAdd(&g_cnt[d0.w], 1);
        atomicAdd(&g_cnt[d1.x], 1); atomicAdd(&g_cnt[d1.y], 1);
        atomicAdd(&g_cnt[d1.z], 1); atomicAdd(&g_cnt[d1.w], 1);
    }
}

// ---------------- fused single-pass scan (WARP-PARALLEL lookback) ----------
// status bits[62:64): 1 = aggregate, 2 = inclusive prefix; value in low 32.
__global__ void scan_fused_kernel() {
    __shared__ int wsum[32];
    __shared__ int s_prefix;
    int tid = threadIdx.x;
    int lane = tid & 31, warp = tid >> 5;
    int b = blockIdx.x;
    int i = b * SCAN_B + tid;
    int v = (i < N_NODES) ? g_cnt[i] : 0;
    int incl = v;
#pragma unroll
    for (int o = 1; o < 32; o <<= 1) {
        int t = __shfl_up_sync(0xffffffffu, incl, o);
        if (lane >= o) incl += t;
    }
    if (lane == 31) wsum[warp] = incl;
    __syncthreads();
    if (warp == 0) {
        int w = wsum[lane];
        int wincl = w;
#pragma unroll
        for (int o = 1; o < 32; o <<= 1) {
            int t = __shfl_up_sync(0xffffffffu, wincl, o);
            if (lane >= o) wincl += t;
        }
        wsum[lane] = wincl - w;                 // exclusive warp offsets
        int total = __shfl_sync(0xffffffffu, wincl, 31);
        if (lane == 0) st_rel(&g_state[b], (1ull << 62) | (unsigned)total);
        // warp-parallel lookback: 32 predecessors per round
        long long running = 0;
        int j = b - 1;
        while (j >= 0) {
            int idx = j - lane;                 // lane 0 = most recent predecessor
            unsigned long long st;
            if (idx >= 0) {
                do { st = ld_acq(&g_state[idx]); } while ((st >> 62) == 0ull);
            } else {
                st = (2ull << 62);              // virtual prefix 0 before block 0
            }
            unsigned pmask = __ballot_sync(0xffffffffu, (st >> 62) == 2ull);
            unsigned val;
            if (pmask) {
                int first = __ffs(pmask) - 1;   // nearest published prefix
                val = (lane <= first) ? (unsigned)st : 0u;
            } else {
                val = (unsigned)st;             // all aggregates; take all 32
            }
#pragma unroll
            for (int o = 16; o >= 1; o >>= 1)
                val += __shfl_xor_sync(0xffffffffu, val, o);
            running += val;
            if (pmask) break;
            j -= 32;
        }
        if (lane == 0) {
            st_rel(&g_state[b], (2ull << 62) | (unsigned)(running + total));
            s_prefix = (int)running;
            if (b == N_SBLK - 1) g_off[N_NODES] = (int)(running + total);
        }
    }
    __syncthreads();
    if (i < N_NODES) {
        int off = s_prefix + incl - v + wsum[warp];
        g_off[i] = off;
        g_cur[i] = off;
        g_inv[i] = 1.0f / (float)(v > 1 ? v : 1);
        g_cnt[i] = 0;                            // recycle for next call
    }
}

// ---------------- scatter (8 edges per thread, batched loads) --------------
__global__ void scatter_kernel(const void* ei) {
    int t = blockIdx.x * blockDim.x + threadIdx.x;
    if (t >= N_EDGES / 8) return;
    int s[8], d[8];
    if (g_is64) {
        const longlong2* sp = (const longlong2*)ei;
        const longlong2* dp = (const longlong2*)((const long long*)ei + N_EDGES);
#pragma unroll
        for (int k = 0; k < 4; k++) {
            longlong2 sv = sp[t * 4 + k];
            longlong2 dv = dp[t * 4 + k];
            s[2 * k] = (int)sv.x; s[2 * k + 1] = (int)sv.y;
            d[2 * k] = (int)dv.x; d[2 * k + 1] = (int)dv.y;
        }
    } else {
        const int4* sp = (const int4*)ei;
        const int4* dp = (const int4*)((const int*)ei + N_EDGES);
#pragma unroll
        for (int k = 0; k < 2; k++) {
            int4 sv = sp[t * 2 + k];
            int4 dv = dp[t * 2 + k];
            s[4 * k] = sv.x; s[4 * k + 1] = sv.y; s[4 * k + 2] = sv.z; s[4 * k + 3] = sv.w;
            d[4 * k] = dv.x; d[4 * k + 1] = dv.y; d[4 * k + 2] = dv.z; d[4 * k + 3] = dv.w;
        }
    }
    int p[8];
#pragma unroll
    for (int k = 0; k < 8; k++) p[k] = atomicAdd(&g_cur[d[k]], 1);
#pragma unroll
    for (int k = 0; k < 8; k++) g_col[p[k]] = s[k];
}

// ---------------- aggregation 1: warp/node, 4 edges/iter -------------------
__global__ void agg1_kernel() {
    int node = blockIdx.x * 8 + (threadIdx.x >> 5);
    if (node >= N_NODES) return;
    int lane = threadIdx.x & 31;
    int q = lane >> 3, p = lane & 7;
    int b = g_off[node], e = g_off[node + 1];
    const uint2* x8 = (const uint2*)g_xh2;
    float4 acc = make_float4(0.f, 0.f, 0.f, 0.f);
    for (int i = b + q; i < e; i += 4) {
        int s = g_col[i];
        uint2 raw = x8[s * 8 + p];
        __half2 h0 = *(__half2*)&raw.x;
        __half2 h1 = *(__half2*)&raw.y;
        float2 f0 = __half22float2(h0), f1 = __half22float2(h1);
        acc.x += f0.x; acc.y += f0.y; acc.z += f1.x; acc.w += f1.y;
    }
#pragma unroll
    for (int off = 8; off <= 16; off <<= 1) {
        acc.x += __shfl_xor_sync(0xffffffffu, acc.x, off);
        acc.y += __shfl_xor_sync(0xffffffffu, acc.y, off);
        acc.z += __shfl_xor_sync(0xffffffffu, acc.z, off);
        acc.w += __shfl_xor_sync(0xffffffffu, acc.w, off);
    }
    if (lane < 8)
        *(float4*)&g_agg1[node * 32 + p * 4] = acc;
}

// ---------------- layer1 GEMM: h = relu([agg1*inv | x] @ [W1l|W1r]^T + b1) -
__global__ void gemm1_mma(const float* __restrict__ b1) {
    __shared__ __half sA[64 * 72];
    __shared__ __half sB[128 * 72];
    int tid = threadIdx.x, lane = tid & 31, warp = tid >> 5;
    int node0 = blockIdx.x * 64;

    for (int idx = tid; idx < 1024; idx += 128) {
        int row = idx >> 3, c8 = (idx & 7) * 8;
        *(uint4*)&sB[row * 72 + c8] = *(const uint4*)&g_w1h[row * 64 + c8];
    }
    for (int idx = tid; idx < 512; idx += 128) {
        int row = idx >> 3, s4 = (idx & 7) * 4;
        int gn = node0 + row;
        float4 v = make_float4(0.f, 0.f, 0.f, 0.f);
        float sc = 0.f;
        if (gn < N_NODES) { v = *(const float4*)&g_agg1[gn * 32 + s4]; sc = g_inv[gn]; }
        __half2 h0 = __floats2half2_rn(v.x * sc, v.y * sc);
        __half2 h1 = __floats2half2_rn(v.z * sc, v.w * sc);
        uint2 pk;
        pk.x = *(unsigned*)&h0; pk.y = *(unsigned*)&h1;
        *(uint2*)&sA[row * 72 + s4] = pk;
    }
    for (int idx = tid; idx < 256; idx += 128) {
        int row = idx >> 2, qq = idx & 3;
        int gn = node0 + row;
        uint4 v = make_uint4(0u, 0u, 0u, 0u);
        if (gn < N_NODES) v = ((const uint4*)g_xh2)[gn * 4 + qq];
        *(uint4*)&sA[row * 72 + 32 + qq * 8] = v;
    }
    __syncthreads();

    float d[16][4];
#pragma unroll
    for (int t = 0; t < 16; t++)
        d[t][0] = d[t][1] = d[t][2] = d[t][3] = 0.f;

    int ar = (lane & 7) + ((lane >> 3) & 1) * 8;
    int ac = (lane >> 4) * 8;
    int br = lane & 7;
    int bc = ((lane >> 3) & 1) * 8;

#pragma unroll
    for (int ks = 0; ks < 4; ks++) {
        int k0 = ks * 16;
        unsigned a0, a1, a2, a3;
        unsigned addrA = smem_u32(&sA[(warp * 16 + ar) * 72 + k0 + ac]);
        LDMATRIX_X4(a0, a1, a2, a3, addrA);
#pragma unroll
        for (int t = 0; t < 16; t++) {
            unsigned b0, b1r;
            unsigned addrB = smem_u32(&sB[(t * 8 + br) * 72 + k0 + bc]);
            LDMATRIX_X2(b0, b1r, addrB);
            MMA16816(d[t], a0, a1, a2, a3, b0, b1r);
        }
    }

    int g = lane >> 2, tg = lane & 3;
    int nA = node0 + warp * 16 + g;
    int nB = nA + 8;
#pragma unroll
    for (int t = 0; t < 16; t++) {
        int col = t * 8 + tg * 2;
        float bx = b1[col], by = b1[col + 1];
        if (nA < N_NODES) {
            __half2 h = __floats2half2_rn(fmaxf(d[t][0] + bx, 0.f),
                                          fmaxf(d[t][1] + by, 0.f));
            *(__half2*)&g_hf[nA * 128 + col] = h;
        }
        if (nB < N_NODES) {
            __half2 h = __floats2half2_rn(fmaxf(d[t][2] + bx, 0.f),
                                          fmaxf(d[t][3] + by, 0.f));
            *(__half2*)&g_hf[nB * 128 + col] = h;
        }
    }
}

// ---------------- gemm_pr: p = h@W2l^T (fp16) AND out = h@W2r^T + b2 -------
__global__ void gemm_pr_mma(const float* __restrict__ b2, float* __restrict__ out) {
    __shared__ __half sA[128 * 72];
    __shared__ __half sB[32 * 264];    // [out][k 0..255] = [W2l | W2r]
    int tid = threadIdx.x, lane = tid & 31, warp = tid >> 5;
    int node0 = blockIdx.x * 128;

    for (int idx = tid; idx < 1024; idx += 128) {
        int row = idx >> 5, s8 = (idx & 31) * 8;
        *(uint4*)&sB[row * 264 + s8] = *(const uint4*)&g_w2h[row * 256 + s8];
    }

    float dp[8][4], dr[8][4];
#pragma unroll
    for (int t = 0; t < 8; t++) {
        dp[t][0] = dp[t][1] = dp[t][2] = dp[t][3] = 0.f;
        dr[t][0] = dr[t][1] = dr[t][2] = dr[t][3] = 0.f;
    }

    int ar = (lane & 7) + ((lane >> 3) & 1) * 8;
    int ac = (lane >> 4) * 8;
    int br = lane & 7;
    int bc = ((lane >> 3) & 1) * 8;

    for (int chunk = 0; chunk < 2; chunk++) {
        if (chunk) __syncthreads();
        for (int idx = tid; idx < 1024; idx += 128) {
            int row = idx >> 3, qq = idx & 7;
            int gn = node0 + row;
            uint4 v = make_uint4(0u, 0u, 0u, 0u);
            if (gn < N_NODES) v = ((const uint4*)g_hf)[gn * 16 + chunk * 8 + qq];
            *(uint4*)&sA[row * 72 + qq * 8] = v;
        }
        __syncthreads();
#pragma unroll
        for (int ks = 0; ks < 4; ks++) {
            int k0 = ks * 16;
            unsigned bl[4][2], brg[4][2];
#pragma unroll
            for (int nt = 0; nt < 4; nt++) {
                unsigned aL = smem_u32(&sB[(nt * 8 + br) * 264 + chunk * 64 + k0 + bc]);
                LDMATRIX_X2(bl[nt][0], bl[nt][1], aL);
                unsigned aR = smem_u32(&sB[(nt * 8 + br) * 264 + 128 + chunk * 64 + k0 + bc]);
                LDMATRIX_X2(brg[nt][0], brg[nt][1], aR);
            }
#pragma unroll
            for (int mt = 0; mt < 2; mt++) {
                unsigned a0, a1, a2, a3;
                unsigned addrA = smem_u32(&sA[(warp * 32 + mt * 16 + ar) * 72 + k0 + ac]);
                LDMATRIX_X4(a0, a1, a2, a3, addrA);
#pragma unroll
                for (int nt = 0; nt < 4; nt++) {
                    MMA16816(dp[mt * 4 + nt], a0, a1, a2, a3, bl[nt][0], bl[nt][1]);
                    MMA16816(dr[mt * 4 + nt], a0, a1, a2, a3, brg[nt][0], brg[nt][1]);
                }
            }
        }
    }

    int g = lane >> 2, tg = lane & 3;
#pragma unroll
    for (int mt = 0; mt < 2; mt++) {
        int nA = node0 + warp * 32 + mt * 16 + g;
        int nB = nA + 8;
#pragma unroll
        for (int nt = 0; nt < 4; nt++) {
            int col = nt * 8 + tg * 2;
            float bx = b2[col], by = b2[col + 1];
            float* pp = dp[mt * 4 + nt];
            float* rr = dr[mt * 4 + nt];
            if (nA < N_NODES) {
                __half2 h = __floats2half2_rn(pp[0], pp[1]);
                *(__half2*)&g_pf[nA * 32 + col] = h;
                float2 o = make_float2(rr[0] + bx, rr[1] + by);
                *(float2*)&out[nA * 32 + col] = o;
            }
            if (nB < N_NODES) {
                __half2 h = __floats2half2_rn(pp[2], pp[3]);
                *(__half2*)&g_pf[nB * 32 + col] = h;
                float2 o = make_float2(rr[2] + bx, rr[3] + by);
                *(float2*)&out[nB * 32 + col] = o;
            }
        }
    }
}

// ---------------- agg2p_add: out += mean_agg(p), in-place ------------------
__global__ void agg2p_add_kernel(float* __restrict__ out) {
    int node = blockIdx.x * 8 + (threadIdx.x >> 5);
    if (node >= N_NODES) return;
    int lane = threadIdx.x & 31;
    int q = lane >> 3, p = lane & 7;
    int b = g_off[node], e = g_off[node + 1];
    const uint2* p8 = (const uint2*)g_pf;
    float4 acc = make_float4(0.f, 0.f, 0.f, 0.f);
    for (int i = b + q; i < e; i += 4) {
        int s = g_col[i];
        uint2 raw = p8[s * 8 + p];
        __half2 h0 = *(__half2*)&raw.x;
        __half2 h1 = *(__half2*)&raw.y;
        float2 f0 = __half22float2(h0), f1 = __half22float2(h1);
        acc.x += f0.x; acc.y += f0.y; acc.z += f1.x; acc.w += f1.y;
    }
#pragma unroll
    for (int off = 8; off <= 16; off <<= 1) {
        acc.x += __shfl_xor_sync(0xffffffffu, acc.x, off);
        acc.y += __shfl_xor_sync(0xffffffffu, acc.y, off);
        acc.z += __shfl_xor_sync(0xffffffffu, acc.z, off);
        acc.w += __shfl_xor_sync(0xffffffffu, acc.w, off);
    }
    if (lane < 8) {
        float sc = g_inv[node];
        float4 cur = *(float4*)&out[node * 32 + p * 4];
        cur.x += acc.x * sc; cur.y += acc.y * sc;
        cur.z += acc.z * sc; cur.w += acc.w * sc;
        *(float4*)&out[node * 32 + p * 4] = cur;
    }
}

// ---------------- launch ---------------------------------------------------
extern "C" void kernel_launch(void* const* d_in, const int* in_sizes, int n_in,
                              void* d_out, int out_size) {
    const float* x   = (const float*)d_in[0];
    const void*  ei  = d_in[1];
    const float* W1l = (const float*)d_in[2];
    const float* W1r = (const float*)d_in[3];
    const float* b1  = (const float*)d_in[4];
    const float* W2l = (const float*)d_in[5];
    const float* W2r = (const float*)d_in[6];
    const float* b2  = (const float*)d_in[7];
    float* out = (float*)d_out;

    const int TB = 256;
    int nb_e8 = (N_EDGES / 8 + TB - 1) / TB;          // 782

    prep_kernel<<<PB_TOT, TB>>>(x, W1l, W1r, W2l, W2r, (const unsigned int*)ei);
    hist_kernel<<<nb_e8, TB>>>(ei);
    scan_fused_kernel<<<N_SBLK, SCAN_B>>>();
    scatter_kernel<<<nb_e8, TB>>>(ei);

    agg1_kernel<<<(N_NODES + 7) / 8, TB>>>();
    gemm1_mma<<<(N_NODES + 63) / 64, 128>>>(b1);
    gemm_pr_mma<<<(N_NODES + 127) / 128, 128>>>(b2, out);
    agg2p_add_kernel<<<(N_NODES + 7) / 8, TB>>>(out);
}

// round 13
// speedup vs baseline: 1.0400x; 1.0400x over previous
#include <cuda_runtime.h>
#include <cuda_fp16.h>

#define N_NODES 100000
#define N_EDGES 1600000
#define IN_CH   32
#define HID     128
#define OUT_CH  32
#define SCAN_B  1024
#define N_SBLK  ((N_NODES + SCAN_B - 1) / SCAN_B)   // 98

// prep_kernel block ranges (xhalf | w1 | w2 | hist)
#define PB_XHALF 3125              // 3125*512 = 1.6M half2
#define PB_W1    (PB_XHALF + 32)
#define PB_W2    (PB_W1 + 32)
#define PB_HIST  (PB_W2 + 3125)    // 3125*256 threads * 2 edges = 1.6M edges
#define PB_TOT   PB_HIST

// ---------------- scratch (device globals; no allocation allowed) ----------
__device__ __align__(16) int    g_cnt[N_NODES];           // zero-recycled each call
__device__ __align__(16) int    g_off[N_NODES + 1];
__device__ __align__(16) int    g_cur[N_NODES];
__device__ __align__(16) int    g_col[N_EDGES];
__device__ __align__(16) float  g_inv[N_NODES];
__device__ __align__(8)  unsigned long long g_state[N_SBLK]; // lookback state
__device__ __align__(16) __half2 g_xh2[N_NODES * 16];     // x fp16, 64B rows
__device__ __align__(16) float  g_agg1[N_NODES * IN_CH];  // fp32 sum, L1
__device__ __align__(16) __half g_hf[N_NODES * HID];      // relu(L1) fp16
__device__ __align__(16) __half g_pf[N_NODES * OUT_CH];   // p = h @ W2l^T fp16
__device__ __align__(16) __half g_w1h[128 * 64];          // [W1l | W1r] fp16
__device__ __align__(16) __half g_w2h[32 * 256];          // [W2l | W2r] fp16
__device__ int g_is64;

static __device__ __forceinline__ unsigned smem_u32(const void* p) {
    unsigned r;
    asm("{ .reg .u64 t; cvta.to.shared.u64 t, %1; cvt.u32.u64 %0, t; }"
        : "=r"(r) : "l"(p));
    return r;
}
static __device__ __forceinline__ unsigned long long ld_acq(unsigned long long* p) {
    unsigned long long v;
    asm volatile("ld.acquire.gpu.u64 %0, [%1];" : "=l"(v) : "l"(p) : "memory");
    return v;
}
static __device__ __forceinline__ void st_rel(unsigned long long* p, unsigned long long v) {
    asm volatile("st.release.gpu.u64 [%0], %1;" :: "l"(p), "l"(v) : "memory");
}

#define LDMATRIX_X4(a0,a1,a2,a3,addr) \
    asm volatile("ldmatrix.sync.aligned.m8n8.x4.shared.b16 {%0,%1,%2,%3}, [%4];" \
        : "=r"(a0),"=r"(a1),"=r"(a2),"=r"(a3) : "r"(addr))
#define LDMATRIX_X2(b0,b1,addr) \
    asm volatile("ldmatrix.sync.aligned.m8n8.x2.shared.b16 {%0,%1}, [%2];" \
        : "=r"(b0),"=r"(b1) : "r"(addr))
#define MMA16816(d,a0,a1,a2,a3,b0,b1) \
    asm volatile("mma.sync.aligned.m16n8k16.row.col.f32.f16.f16.f32 " \
        "{%0,%1,%2,%3}, {%4,%5,%6,%7}, {%8,%9}, {%0,%1,%2,%3};" \
        : "+f"(d[0]),"+f"(d[1]),"+f"(d[2]),"+f"(d[3]) \
        : "r"(a0),"r"(a1),"r"(a2),"r"(a3),"r"(b0),"r"(b1))

// ---------------- detect + state reset (must precede prep) -----------------
__global__ void detect_kernel(const unsigned int* __restrict__ ei32) {
    __shared__ int flag;
    int tid = threadIdx.x;
    if (tid == 0) flag = 0;
    if (tid < N_SBLK) g_state[tid] = 0ull;
    __syncthreads();
    if (tid < 128 && ei32[2 * tid + 1] != 0u) flag = 1;
    __syncthreads();
    if (tid == 0) g_is64 = flag ? 0 : 1;
}

// ---------------- prep: xhalf + wconv1 + wconv2 + HIST (overlapped) --------
__global__ void prep_kernel(const float* __restrict__ x,
                            const float* __restrict__ W1l,
                            const float* __restrict__ W1r,
                            const float* __restrict__ W2l,
                            const float* __restrict__ W2r,
                            const void* __restrict__ ei) {
    int b = blockIdx.x, tid = threadIdx.x;
    if (b < PB_XHALF) {
        int i = b * 512 + tid;
        float2 v0 = ((const float2*)x)[i];
        g_xh2[i] = __floats2half2_rn(v0.x, v0.y);
        int i2 = i + 256;
        float2 v1 = ((const float2*)x)[i2];
        g_xh2[i2] = __floats2half2_rn(v1.x, v1.y);
    } else if (b < PB_W1) {
        int i = (b - PB_XHALF) * 256 + tid;     // 8192 = 128*64
        int row = i >> 6, k = i & 63;
        float v = (k < 32) ? W1l[row * 32 + k] : W1r[row * 32 + (k - 32)];
        g_w1h[i] = __float2half_rn(v);
    } else if (b < PB_W2) {
        int i = (b - PB_W1) * 256 + tid;        // 8192 = 32*256
        int row = i >> 8, k = i & 255;
        float v = (k < 128) ? W2l[row * 128 + k] : W2r[row * 128 + (k - 128)];
        g_w2h[i] = __float2half_rn(v);
    } else {
        int e2 = (b - PB_W2) * 256 + tid;       // 2 edges per thread
        if (e2 < N_EDGES / 2) {
            if (g_is64) {
                longlong2 d = ((const longlong2*)((const long long*)ei + N_EDGES))[e2];
                atomicAdd(&g_cnt[(int)d.x], 1);
                atomicAdd(&g_cnt[(int)d.y], 1);
            } else {
                int2 d = ((const int2*)((const int*)ei + N_EDGES))[e2];
                atomicAdd(&g_cnt[d.x], 1);
                atomicAdd(&g_cnt[d.y], 1);
            }
        }
    }
}

// ---------------- fused single-pass scan (warp-parallel lookback) ----------
// status bits[62:64): 1 = aggregate, 2 = inclusive prefix; value in low 32.
__global__ void scan_fused_kernel() {
    __shared__ int wsum[32];
    __shared__ int s_prefix;
    int tid = threadIdx.x;
    int lane = tid & 31, warp = tid >> 5;
    int b = blockIdx.x;
    int i = b * SCAN_B + tid;
    int v = (i < N_NODES) ? g_cnt[i] : 0;
    int incl = v;
#pragma unroll
    for (int o = 1; o < 32; o <<= 1) {
        int t = __shfl_up_sync(0xffffffffu, incl, o);
        if (lane >= o) incl += t;
    }
    if (lane == 31) wsum[warp] = incl;
    __syncthreads();
    if (warp == 0) {
        int w = wsum[lane];
        int wincl = w;
#pragma unroll
        for (int o = 1; o < 32; o <<= 1) {
            int t = __shfl_up_sync(0xffffffffu, wincl, o);
            if (lane >= o) wincl += t;
        }
        wsum[lane] = wincl - w;                 // exclusive warp offsets
        int total = __shfl_sync(0xffffffffu, wincl, 31);
        if (lane == 0) st_rel(&g_state[b], (1ull << 62) | (unsigned)total);
        long long running = 0;
        int j = b - 1;
        while (j >= 0) {
            int idx = j - lane;
            unsigned long long st;
            if (idx >= 0) {
                do { st = ld_acq(&g_state[idx]); } while ((st >> 62) == 0ull);
            } else {
                st = (2ull << 62);
            }
            unsigned pmask = __ballot_sync(0xffffffffu, (st >> 62) == 2ull);
            unsigned val;
            if (pmask) {
                int first = __ffs(pmask) - 1;
                val = (lane <= first) ? (unsigned)st : 0u;
            } else {
                val = (unsigned)st;
            }
#pragma unroll
            for (int o = 16; o >= 1; o >>= 1)
                val += __shfl_xor_sync(0xffffffffu, val, o);
            running += val;
            if (pmask) break;
            j -= 32;
        }
        if (lane == 0) {
            st_rel(&g_state[b], (2ull << 62) | (unsigned)(running + total));
            s_prefix = (int)running;
            if (b == N_SBLK - 1) g_off[N_NODES] = (int)(running + total);
        }
    }
    __syncthreads();
    if (i < N_NODES) {
        int off = s_prefix + incl - v + wsum[warp];
        g_off[i] = off;
        g_cur[i] = off;
        g_inv[i] = 1.0f / (float)(v > 1 ? v : 1);
        g_cnt[i] = 0;                            // recycle for next call
    }
}

// ---------------- scatter (2 edges per thread — measured best) -------------
__global__ void scatter_kernel(const void* ei) {
    int e2 = blockIdx.x * blockDim.x + threadIdx.x;
    if (e2 >= N_EDGES / 2) return;
    if (g_is64) {
        longlong2 s = ((const longlong2*)ei)[e2];
        longlong2 d = ((const longlong2*)((const long long*)ei + N_EDGES))[e2];
        int p0 = atomicAdd(&g_cur[(int)d.x], 1);
        g_col[p0] = (int)s.x;
        int p1 = atomicAdd(&g_cur[(int)d.y], 1);
        g_col[p1] = (int)s.y;
    } else {
        int2 s = ((const int2*)ei)[e2];
        int2 d = ((const int2*)((const int*)ei + N_EDGES))[e2];
        int p0 = atomicAdd(&g_cur[d.x], 1);
        g_col[p0] = s.x;
        int p1 = atomicAdd(&g_cur[d.y], 1);
        g_col[p1] = s.y;
    }
}

// ---------------- aggregation 1: warp/node, 4 edges/iter -------------------
__global__ void agg1_kernel() {
    int node = blockIdx.x * 8 + (threadIdx.x >> 5);
    if (node >= N_NODES) return;
    int lane = threadIdx.x & 31;
    int q = lane >> 3, p = lane & 7;
    int b = g_off[node], e = g_off[node + 1];
    const uint2* x8 = (const uint2*)g_xh2;
    float4 acc = make_float4(0.f, 0.f, 0.f, 0.f);
    for (int i = b + q; i < e; i += 4) {
        int s = g_col[i];
        uint2 raw = x8[s * 8 + p];
        __half2 h0 = *(__half2*)&raw.x;
        __half2 h1 = *(__half2*)&raw.y;
        float2 f0 = __half22float2(h0), f1 = __half22float2(h1);
        acc.x += f0.x; acc.y += f0.y; acc.z += f1.x; acc.w += f1.y;
    }
#pragma unroll
    for (int off = 8; off <= 16; off <<= 1) {
        acc.x += __shfl_xor_sync(0xffffffffu, acc.x, off);
        acc.y += __shfl_xor_sync(0xffffffffu, acc.y, off);
        acc.z += __shfl_xor_sync(0xffffffffu, acc.z, off);
        acc.w += __shfl_xor_sync(0xffffffffu, acc.w, off);
    }
    if (lane < 8)
        *(float4*)&g_agg1[node * 32 + p * 4] = acc;
}

// ---------------- layer1 GEMM: h = relu([agg1*inv | x] @ [W1l|W1r]^T + b1) -
__global__ void gemm1_mma(const float* __restrict__ b1) {
    __shared__ __half sA[64 * 72];
    __shared__ __half sB[128 * 72];
    int tid = threadIdx.x, lane = tid & 31, warp = tid >> 5;
    int node0 = blockIdx.x * 64;

    for (int idx = tid; idx < 1024; idx += 128) {
        int row = idx >> 3, c8 = (idx & 7) * 8;
        *(uint4*)&sB[row * 72 + c8] = *(const uint4*)&g_w1h[row * 64 + c8];
    }
    for (int idx = tid; idx < 512; idx += 128) {
        int row = idx >> 3, s4 = (idx & 7) * 4;
        int gn = node0 + row;
        float4 v = make_float4(0.f, 0.f, 0.f, 0.f);
        float sc = 0.f;
        if (gn < N_NODES) { v = *(const float4*)&g_agg1[gn * 32 + s4]; sc = g_inv[gn]; }
        __half2 h0 = __floats2half2_rn(v.x * sc, v.y * sc);
        __half2 h1 = __floats2half2_rn(v.z * sc, v.w * sc);
        uint2 pk;
        pk.x = *(unsigned*)&h0; pk.y = *(unsigned*)&h1;
        *(uint2*)&sA[row * 72 + s4] = pk;
    }
    for (int idx = tid; idx < 256; idx += 128) {
        int row = idx >> 2, qq = idx & 3;
        int gn = node0 + row;
        uint4 v = make_uint4(0u, 0u, 0u, 0u);
        if (gn < N_NODES) v = ((const uint4*)g_xh2)[gn * 4 + qq];
        *(uint4*)&sA[row * 72 + 32 + qq * 8] = v;
    }
    __syncthreads();

    float d[16][4];
#pragma unroll
    for (int t = 0; t < 16; t++)
        d[t][0] = d[t][1] = d[t][2] = d[t][3] = 0.f;

    int ar = (lane & 7) + ((lane >> 3) & 1) * 8;
    int ac = (lane >> 4) * 8;
    int br = lane & 7;
    int bc = ((lane >> 3) & 1) * 8;

#pragma unroll
    for (int ks = 0; ks < 4; ks++) {
        int k0 = ks * 16;
        unsigned a0, a1, a2, a3;
        unsigned addrA = smem_u32(&sA[(warp * 16 + ar) * 72 + k0 + ac]);
        LDMATRIX_X4(a0, a1, a2, a3, addrA);
#pragma unroll
        for (int t = 0; t < 16; t++) {
            unsigned b0, b1r;
            unsigned addrB = smem_u32(&sB[(t * 8 + br) * 72 + k0 + bc]);
            LDMATRIX_X2(b0, b1r, addrB);
            MMA16816(d[t], a0, a1, a2, a3, b0, b1r);
        }
    }

    int g = lane >> 2, tg = lane & 3;
    int nA = node0 + warp * 16 + g;
    int nB = nA + 8;
#pragma unroll
    for (int t = 0; t < 16; t++) {
        int col = t * 8 + tg * 2;
        float bx = b1[col], by = b1[col + 1];
        if (nA < N_NODES) {
            __half2 h = __floats2half2_rn(fmaxf(d[t][0] + bx, 0.f),
                                          fmaxf(d[t][1] + by, 0.f));
            *(__half2*)&g_hf[nA * 128 + col] = h;
        }
        if (nB < N_NODES) {
            __half2 h = __floats2half2_rn(fmaxf(d[t][2] + bx, 0.f),
                                          fmaxf(d[t][3] + by, 0.f));
            *(__half2*)&g_hf[nB * 128 + col] = h;
        }
    }
}

// ---------------- gemm_pr: p = h@W2l^T (fp16) AND out = h@W2r^T + b2 -------
__global__ void gemm_pr_mma(const float* __restrict__ b2, float* __restrict__ out) {
    __shared__ __half sA[128 * 72];
    __shared__ __half sB[32 * 264];    // [out][k 0..255] = [W2l | W2r]
    int tid = threadIdx.x, lane = tid & 31, warp = tid >> 5;
    int node0 = blockIdx.x * 128;

    for (int idx = tid; idx < 1024; idx += 128) {
        int row = idx >> 5, s8 = (idx & 31) * 8;
        *(uint4*)&sB[row * 264 + s8] = *(const uint4*)&g_w2h[row * 256 + s8];
    }

    float dp[8][4], dr[8][4];
#pragma unroll
    for (int t = 0; t < 8; t++) {
        dp[t][0] = dp[t][1] = dp[t][2] = dp[t][3] = 0.f;
        dr[t][0] = dr[t][1] = dr[t][2] = dr[t][3] = 0.f;
    }

    int ar = (lane & 7) + ((lane >> 3) & 1) * 8;
    int ac = (lane >> 4) * 8;
    int br = lane & 7;
    int bc = ((lane >> 3) & 1) * 8;

    for (int chunk = 0; chunk < 2; chunk++) {
        if (chunk) __syncthreads();
        for (int idx = tid; idx < 1024; idx += 128) {
            int row = idx >> 3, qq = idx & 7;
            int gn = node0 + row;
            uint4 v = make_uint4(0u, 0u, 0u, 0u);
            if (gn < N_NODES) v = ((const uint4*)g_hf)[gn * 16 + chunk * 8 + qq];
            *(uint4*)&sA[row * 72 + qq * 8] = v;
        }
        __syncthreads();
#pragma unroll
        for (int ks = 0; ks < 4; ks++) {
            int k0 = ks * 16;
            unsigned bl[4][2], brg[4][2];
#pragma unroll
            for (int nt = 0; nt < 4; nt++) {
                unsigned aL = smem_u32(&sB[(nt * 8 + br) * 264 + chunk * 64 + k0 + bc]);
                LDMATRIX_X2(bl[nt][0], bl[nt][1], aL);
                unsigned aR = smem_u32(&sB[(nt * 8 + br) * 264 + 128 + chunk * 64 + k0 + bc]);
                LDMATRIX_X2(brg[nt][0], brg[nt][1], aR);
            }
#pragma unroll
            for (int mt = 0; mt < 2; mt++) {
                unsigned a0, a1, a2, a3;
                unsigned addrA = smem_u32(&sA[(warp * 32 + mt * 16 + ar) * 72 + k0 + ac]);
                LDMATRIX_X4(a0, a1, a2, a3, addrA);
#pragma unroll
                for (int nt = 0; nt < 4; nt++) {
                    MMA16816(dp[mt * 4 + nt], a0, a1, a2, a3, bl[nt][0], bl[nt][1]);
                    MMA16816(dr[mt * 4 + nt], a0, a1, a2, a3, brg[nt][0], brg[nt][1]);
                }
            }
        }
    }

    int g = lane >> 2, tg = lane & 3;
#pragma unroll
    for (int mt = 0; mt < 2; mt++) {
        int nA = node0 + warp * 32 + mt * 16 + g;
        int nB = nA + 8;
#pragma unroll
        for (int nt = 0; nt < 4; nt++) {
            int col = nt * 8 + tg * 2;
            float bx = b2[col], by = b2[col + 1];
            float* pp = dp[mt * 4 + nt];
            float* rr = dr[mt * 4 + nt];
            if (nA < N_NODES) {
                __half2 h = __floats2half2_rn(pp[0], pp[1]);
                *(__half2*)&g_pf[nA * 32 + col] = h;
                float2 o = make_float2(rr[0] + bx, rr[1] + by);
                *(float2*)&out[nA * 32 + col] = o;
            }
            if (nB < N_NODES) {
                __half2 h = __floats2half2_rn(pp[2], pp[3]);
                *(__half2*)&g_pf[nB * 32 + col] = h;
                float2 o = make_float2(rr[2] + bx, rr[3] + by);
                *(float2*)&out[nB * 32 + col] = o;
            }
        }
    }
}

// ---------------- agg2p_add: out += mean_agg(p), in-place ------------------
__global__ void agg2p_add_kernel(float* __restrict__ out) {
    int node = blockIdx.x * 8 + (threadIdx.x >> 5);
    if (node >= N_NODES) return;
    int lane = threadIdx.x & 31;
    int q = lane >> 3, p = lane & 7;
    int b = g_off[node], e = g_off[node + 1];
    const uint2* p8 = (const uint2*)g_pf;
    float4 acc = make_float4(0.f, 0.f, 0.f, 0.f);
    for (int i = b + q; i < e; i += 4) {
        int s = g_col[i];
        uint2 raw = p8[s * 8 + p];
        __half2 h0 = *(__half2*)&raw.x;
        __half2 h1 = *(__half2*)&raw.y;
        float2 f0 = __half22float2(h0), f1 = __half22float2(h1);
        acc.x += f0.x; acc.y += f0.y; acc.z += f1.x; acc.w += f1.y;
    }
#pragma unroll
    for (int off = 8; off <= 16; off <<= 1) {
        acc.x += __shfl_xor_sync(0xffffffffu, acc.x, off);
        acc.y += __shfl_xor_sync(0xffffffffu, acc.y, off);
        acc.z += __shfl_xor_sync(0xffffffffu, acc.z, off);
        acc.w += __shfl_xor_sync(0xffffffffu, acc.w, off);
    }
    if (lane < 8) {
        float sc = g_inv[node];
        float4 cur = *(float4*)&out[node * 32 + p * 4];
        cur.x += acc.x * sc; cur.y += acc.y * sc;
        cur.z += acc.z * sc; cur.w += acc.w * sc;
        *(float4*)&out[node * 32 + p * 4] = cur;
    }
}

// ---------------- launch ---------------------------------------------------
extern "C" void kernel_launch(void* const* d_in, const int* in_sizes, int n_in,
                              void* d_out, int out_size) {
    const float* x   = (const float*)d_in[0];
    const void*  ei  = d_in[1];
    const float* W1l = (const float*)d_in[2];
    const float* W1r = (const float*)d_in[3];
    const float* b1  = (const float*)d_in[4];
    const float* W2l = (const float*)d_in[5];
    const float* W2r = (const float*)d_in[6];
    const float* b2  = (const float*)d_in[7];
    float* out = (float*)d_out;

    const int TB = 256;
    int nb_e2 = (N_EDGES / 2 + TB - 1) / TB;          // 3125

    detect_kernel<<<1, 128>>>((const unsigned int*)ei);
    prep_kernel<<<PB_TOT, TB>>>(x, W1l, W1r, W2l, W2r, ei);  // xhalf+w+HIST overlapped
    scan_fused_kernel<<<N_SBLK, SCAN_B>>>();
    scatter_kernel<<<nb_e2, TB>>>(ei);

    agg1_kernel<<<(N_NODES + 7) / 8, TB>>>();
    gemm1_mma<<<(N_NODES + 63) / 64, 128>>>(b1);
    gemm_pr_mma<<<(N_NODES + 127) / 128, 128>>>(b2, out);
    agg2p_add_kernel<<<(N_NODES + 7) / 8, TB>>>(out);
}

// round 14
// speedup vs baseline: 1.0514x; 1.0110x over previous
#include <cuda_runtime.h>
#include <cuda_fp16.h>

#define N_NODES 100000
#define N_EDGES 1600000
#define IN_CH   32
#define HID     128
#define OUT_CH  32
#define SCAN_B  1024
#define N_SBLK  ((N_NODES + SCAN_B - 1) / SCAN_B)   // 98

// prep_kernel block ranges (xhalf | w1 | w2 | hist)
#define PB_XHALF 3125              // 3125*512 = 1.6M half2
#define PB_W1    (PB_XHALF + 32)
#define PB_W2    (PB_W1 + 32)
#define PB_HIST  (PB_W2 + 1563)    // 1563*256 threads * 4 edges >= 1.6M edges
#define PB_TOT   PB_HIST

// ---------------- scratch (device globals; no allocation allowed) ----------
__device__ __align__(16) int    g_cnt[N_NODES];           // zero-recycled each call
__device__ __align__(16) int    g_off[N_NODES + 1];
__device__ __align__(16) int    g_rank[N_EDGES];          // within-dst rank per edge
__device__ __align__(16) int    g_col[N_EDGES];
__device__ __align__(16) float  g_inv[N_NODES];
__device__ __align__(8)  unsigned long long g_state[N_SBLK]; // lookback state
__device__ __align__(16) __half2 g_xh2[N_NODES * 16];     // x fp16, 64B rows
__device__ __align__(16) float  g_agg1[N_NODES * IN_CH];  // fp32 sum, L1
__device__ __align__(16) __half g_hf[N_NODES * HID];      // relu(L1) fp16
__device__ __align__(16) __half g_pf[N_NODES * OUT_CH];   // p = h @ W2l^T fp16
__device__ __align__(16) __half g_w1h[128 * 64];          // [W1l | W1r] fp16
__device__ __align__(16) __half g_w2h[32 * 256];          // [W2l | W2r] fp16

static __device__ __forceinline__ unsigned smem_u32(const void* p) {
    unsigned r;
    asm("{ .reg .u64 t; cvta.to.shared.u64 t, %1; cvt.u32.u64 %0, t; }"
        : "=r"(r) : "l"(p));
    return r;
}
static __device__ __forceinline__ unsigned long long ld_acq(unsigned long long* p) {
    unsigned long long v;
    asm volatile("ld.acquire.gpu.u64 %0, [%1];" : "=l"(v) : "l"(p) : "memory");
    return v;
}
static __device__ __forceinline__ void st_rel(unsigned long long* p, unsigned long long v) {
    asm volatile("st.release.gpu.u64 [%0], %1;" :: "l"(p), "l"(v) : "memory");
}
// int64 vs int32 edge_index: int64 node ids < 1e5 -> odd 32-bit words all zero.
// 16 odd words, all L1-resident/uniform; P(false positive on int32) ~ 1e-80.
static __device__ __forceinline__ int is64_check(const void* ei) {
    const unsigned* w = (const unsigned*)ei;
    unsigned acc = 0;
#pragma unroll
    for (int k = 1; k < 32; k += 2) acc |= w[k];
    return acc == 0u;
}

#define LDMATRIX_X4(a0,a1,a2,a3,addr) \
    asm volatile("ldmatrix.sync.aligned.m8n8.x4.shared.b16 {%0,%1,%2,%3}, [%4];" \
        : "=r"(a0),"=r"(a1),"=r"(a2),"=r"(a3) : "r"(addr))
#define LDMATRIX_X2(b0,b1,addr) \
    asm volatile("ldmatrix.sync.aligned.m8n8.x2.shared.b16 {%0,%1}, [%2];" \
        : "=r"(b0),"=r"(b1) : "r"(addr))
#define MMA16816(d,a0,a1,a2,a3,b0,b1) \
    asm volatile("mma.sync.aligned.m16n8k16.row.col.f32.f16.f16.f32 " \
        "{%0,%1,%2,%3}, {%4,%5,%6,%7}, {%8,%9}, {%0,%1,%2,%3};" \
        : "+f"(d[0]),"+f"(d[1]),"+f"(d[2]),"+f"(d[3]) \
        : "r"(a0),"r"(a1),"r"(a2),"r"(a3),"r"(b0),"r"(b1))

// ---------------- prep: xhalf + wconv + state reset + RANK-HIST ------------
__global__ void prep_kernel(const float* __restrict__ x,
                            const float* __restrict__ W1l,
                            const float* __restrict__ W1r,
                            const float* __restrict__ W2l,
                            const float* __restrict__ W2r,
                            const void* __restrict__ ei) {
    int b = blockIdx.x, tid = threadIdx.x;
    if (b < PB_XHALF) {
        int i = b * 512 + tid;
        float2 v0 = ((const float2*)x)[i];
        g_xh2[i] = __floats2half2_rn(v0.x, v0.y);
        int i2 = i + 256;
        float2 v1 = ((const float2*)x)[i2];
        g_xh2[i2] = __floats2half2_rn(v1.x, v1.y);
    } else if (b < PB_W1) {
        if (b == PB_XHALF && tid < N_SBLK) g_state[tid] = 0ull;  // lookback reset
        int i = (b - PB_XHALF) * 256 + tid;     // 8192 = 128*64
        int row = i >> 6, k = i & 63;
        float v = (k < 32) ? W1l[row * 32 + k] : W1r[row * 32 + (k - 32)];
        g_w1h[i] = __float2half_rn(v);
    } else if (b < PB_W2) {
        int i = (b - PB_W1) * 256 + tid;        // 8192 = 32*256
        int row = i >> 8, k = i & 255;
        float v = (k < 128) ? W2l[row * 128 + k] : W2r[row * 128 + (k - 128)];
        g_w2h[i] = __float2half_rn(v);
    } else {
        // rank-hist: 4 edges/thread; atomicAdd returns within-dst rank.
        int t = (b - PB_W2) * 256 + tid;
        if (t < N_EDGES / 4) {
            int d[4];
            if (is64_check(ei)) {
                const longlong2* dp = (const longlong2*)((const long long*)ei + N_EDGES);
                longlong2 a = dp[t * 2], c = dp[t * 2 + 1];
                d[0] = (int)a.x; d[1] = (int)a.y; d[2] = (int)c.x; d[3] = (int)c.y;
            } else {
                int4 v = ((const int4*)((const int*)ei + N_EDGES))[t];
                d[0] = v.x; d[1] = v.y; d[2] = v.z; d[3] = v.w;
            }
            int4 r;
            r.x = atomicAdd(&g_cnt[d[0]], 1);
            r.y = atomicAdd(&g_cnt[d[1]], 1);
            r.z = atomicAdd(&g_cnt[d[2]], 1);
            r.w = atomicAdd(&g_cnt[d[3]], 1);
            ((int4*)g_rank)[t] = r;             // coalesced 16B store
        }
    }
}

// ---------------- fused single-pass scan (warp-parallel lookback) ----------
// status bits[62:64): 1 = aggregate, 2 = inclusive prefix; value in low 32.
__global__ void scan_fused_kernel() {
    __shared__ int wsum[32];
    __shared__ int s_prefix;
    int tid = threadIdx.x;
    int lane = tid & 31, warp = tid >> 5;
    int b = blockIdx.x;
    int i = b * SCAN_B + tid;
    int v = (i < N_NODES) ? g_cnt[i] : 0;
    int incl = v;
#pragma unroll
    for (int o = 1; o < 32; o <<= 1) {
        int t = __shfl_up_sync(0xffffffffu, incl, o);
        if (lane >= o) incl += t;
    }
    if (lane == 31) wsum[warp] = incl;
    __syncthreads();
    if (warp == 0) {
        int w = wsum[lane];
        int wincl = w;
#pragma unroll
        for (int o = 1; o < 32; o <<= 1) {
            int t = __shfl_up_sync(0xffffffffu, wincl, o);
            if (lane >= o) wincl += t;
        }
        wsum[lane] = wincl - w;                 // exclusive warp offsets
        int total = __shfl_sync(0xffffffffu, wincl, 31);
        if (lane == 0) st_rel(&g_state[b], (1ull << 62) | (unsigned)total);
        long long running = 0;
        int j = b - 1;
        while (j >= 0) {
            int idx = j - lane;
            unsigned long long st;
            if (idx >= 0) {
                do { st = ld_acq(&g_state[idx]); } while ((st >> 62) == 0ull);
            } else {
                st = (2ull << 62);
            }
            unsigned pmask = __ballot_sync(0xffffffffu, (st >> 62) == 2ull);
            unsigned val;
            if (pmask) {
                int first = __ffs(pmask) - 1;
                val = (lane <= first) ? (unsigned)st : 0u;
            } else {
                val = (unsigned)st;
            }
#pragma unroll
            for (int o = 16; o >= 1; o >>= 1)
                val += __shfl_xor_sync(0xffffffffu, val, o);
            running += val;
            if (pmask) break;
            j -= 32;
        }
        if (lane == 0) {
            st_rel(&g_state[b], (2ull << 62) | (unsigned)(running + total));
            s_prefix = (int)running;
            if (b == N_SBLK - 1) g_off[N_NODES] = (int)(running + total);
        }
    }
    __syncthreads();
    if (i < N_NODES) {
        int off = s_prefix + incl - v + wsum[warp];
        g_off[i] = off;
        g_inv[i] = 1.0f / (float)(v > 1 ? v : 1);
        g_cnt[i] = 0;                            // recycle for next call
    }
}

// ---------------- scatter (ATOMIC-FREE: p = off[d] + rank) -----------------
__global__ void scatter_kernel(const void* ei) {
    int t = blockIdx.x * blockDim.x + threadIdx.x;
    if (t >= N_EDGES / 4) return;
    int s[4], d[4];
    if (is64_check(ei)) {
        const longlong2* sp = (const longlong2*)ei;
        const longlong2* dp = (const longlong2*)((const long long*)ei + N_EDGES);
        longlong2 s0 = sp[t * 2], s1 = sp[t * 2 + 1];
        longlong2 d0 = dp[t * 2], d1 = dp[t * 2 + 1];
        s[0] = (int)s0.x; s[1] = (int)s0.y; s[2] = (int)s1.x; s[3] = (int)s1.y;
        d[0] = (int)d0.x; d[1] = (int)d0.y; d[2] = (int)d1.x; d[3] = (int)d1.y;
    } else {
        int4 sv = ((const int4*)ei)[t];
        int4 dv = ((const int4*)((const int*)ei + N_EDGES))[t];
        s[0] = sv.x; s[1] = sv.y; s[2] = sv.z; s[3] = sv.w;
        d[0] = dv.x; d[1] = dv.y; d[2] = dv.z; d[3] = dv.w;
    }
    int4 rk = ((const int4*)g_rank)[t];
    int p0 = g_off[d[0]] + rk.x;                 // plain loads: deep MLP
    int p1 = g_off[d[1]] + rk.y;
    int p2 = g_off[d[2]] + rk.z;
    int p3 = g_off[d[3]] + rk.w;
    g_col[p0] = s[0];                            // fire-and-forget scattered STG
    g_col[p1] = s[1];
    g_col[p2] = s[2];
    g_col[p3] = s[3];
}

// ---------------- aggregation 1: warp/node, 4 edges/iter -------------------
__global__ void agg1_kernel() {
    int node = blockIdx.x * 8 + (threadIdx.x >> 5);
    if (node >= N_NODES) return;
    int lane = threadIdx.x & 31;
    int q = lane >> 3, p = lane & 7;
    int b = g_off[node], e = g_off[node + 1];
    const uint2* x8 = (const uint2*)g_xh2;
    float4 acc = make_float4(0.f, 0.f, 0.f, 0.f);
    for (int i = b + q; i < e; i += 4) {
        int s = g_col[i];
        uint2 raw = x8[s * 8 + p];
        __half2 h0 = *(__half2*)&raw.x;
        __half2 h1 = *(__half2*)&raw.y;
        float2 f0 = __half22float2(h0), f1 = __half22float2(h1);
        acc.x += f0.x; acc.y += f0.y; acc.z += f1.x; acc.w += f1.y;
    }
#pragma unroll
    for (int off = 8; off <= 16; off <<= 1) {
        acc.x += __shfl_xor_sync(0xffffffffu, acc.x, off);
        acc.y += __shfl_xor_sync(0xffffffffu, acc.y, off);
        acc.z += __shfl_xor_sync(0xffffffffu, acc.z, off);
        acc.w += __shfl_xor_sync(0xffffffffu, acc.w, off);
    }
    if (lane < 8)
        *(float4*)&g_agg1[node * 32 + p * 4] = acc;
}

// ---------------- layer1 GEMM: h = relu([agg1*inv | x] @ [W1l|W1r]^T + b1) -
__global__ void gemm1_mma(const float* __restrict__ b1) {
    __shared__ __half sA[64 * 72];
    __shared__ __half sB[128 * 72];
    int tid = threadIdx.x, lane = tid & 31, warp = tid >> 5;
    int node0 = blockIdx.x * 64;

    for (int idx = tid; idx < 1024; idx += 128) {
        int row = idx >> 3, c8 = (idx & 7) * 8;
        *(uint4*)&sB[row * 72 + c8] = *(const uint4*)&g_w1h[row * 64 + c8];
    }
    for (int idx = tid; idx < 512; idx += 128) {
        int row = idx >> 3, s4 = (idx & 7) * 4;
        int gn = node0 + row;
        float4 v = make_float4(0.f, 0.f, 0.f, 0.f);
        float sc = 0.f;
        if (gn < N_NODES) { v = *(const float4*)&g_agg1[gn * 32 + s4]; sc = g_inv[gn]; }
        __half2 h0 = __floats2half2_rn(v.x * sc, v.y * sc);
        __half2 h1 = __floats2half2_rn(v.z * sc, v.w * sc);
        uint2 pk;
        pk.x = *(unsigned*)&h0; pk.y = *(unsigned*)&h1;
        *(uint2*)&sA[row * 72 + s4] = pk;
    }
    for (int idx = tid; idx < 256; idx += 128) {
        int row = idx >> 2, qq = idx & 3;
        int gn = node0 + row;
        uint4 v = make_uint4(0u, 0u, 0u, 0u);
        if (gn < N_NODES) v = ((const uint4*)g_xh2)[gn * 4 + qq];
        *(uint4*)&sA[row * 72 + 32 + qq * 8] = v;
    }
    __syncthreads();

    float d[16][4];
#pragma unroll
    for (int t = 0; t < 16; t++)
        d[t][0] = d[t][1] = d[t][2] = d[t][3] = 0.f;

    int ar = (lane & 7) + ((lane >> 3) & 1) * 8;
    int ac = (lane >> 4) * 8;
    int br = lane & 7;
    int bc = ((lane >> 3) & 1) * 8;

#pragma unroll
    for (int ks = 0; ks < 4; ks++) {
        int k0 = ks * 16;
        unsigned a0, a1, a2, a3;
        unsigned addrA = smem_u32(&sA[(warp * 16 + ar) * 72 + k0 + ac]);
        LDMATRIX_X4(a0, a1, a2, a3, addrA);
#pragma unroll
        for (int t = 0; t < 16; t++) {
            unsigned b0, b1r;
            unsigned addrB = smem_u32(&sB[(t * 8 + br) * 72 + k0 + bc]);
            LDMATRIX_X2(b0, b1r, addrB);
            MMA16816(d[t], a0, a1, a2, a3, b0, b1r);
        }
    }

    int g = lane >> 2, tg = lane & 3;
    int nA = node0 + warp * 16 + g;
    int nB = nA + 8;
#pragma unroll
    for (int t = 0; t < 16; t++) {
        int col = t * 8 + tg * 2;
        float bx = b1[col], by = b1[col + 1];
        if (nA < N_NODES) {
            __half2 h = __floats2half2_rn(fmaxf(d[t][0] + bx, 0.f),
                                          fmaxf(d[t][1] + by, 0.f));
            *(__half2*)&g_hf[nA * 128 + col] = h;
        }
        if (nB < N_NODES) {
            __half2 h = __floats2half2_rn(fmaxf(d[t][2] + bx, 0.f),
                                          fmaxf(d[t][3] + by, 0.f));
            *(__half2*)&g_hf[nB * 128 + col] = h;
        }
    }
}

// ---------------- gemm_pr: p = h@W2l^T (fp16) AND out = h@W2r^T + b2 -------
__global__ void gemm_pr_mma(const float* __restrict__ b2, float* __restrict__ out) {
    __shared__ __half sA[128 * 72];
    __shared__ __half sB[32 * 264];    // [out][k 0..255] = [W2l | W2r]
    int tid = threadIdx.x, lane = tid & 31, warp = tid >> 5;
    int node0 = blockIdx.x * 128;

    for (int idx = tid; idx < 1024; idx += 128) {
        int row = idx >> 5, s8 = (idx & 31) * 8;
        *(uint4*)&sB[row * 264 + s8] = *(const uint4*)&g_w2h[row * 256 + s8];
    }

    float dp[8][4], dr[8][4];
#pragma unroll
    for (int t = 0; t < 8; t++) {
        dp[t][0] = dp[t][1] = dp[t][2] = dp[t][3] = 0.f;
        dr[t][0] = dr[t][1] = dr[t][2] = dr[t][3] = 0.f;
    }

    int ar = (lane & 7) + ((lane >> 3) & 1) * 8;
    int ac = (lane >> 4) * 8;
    int br = lane & 7;
    int bc = ((lane >> 3) & 1) * 8;

    for (int chunk = 0; chunk < 2; chunk++) {
        if (chunk) __syncthreads();
        for (int idx = tid; idx < 1024; idx += 128) {
            int row = idx >> 3, qq = idx & 7;
            int gn = node0 + row;
            uint4 v = make_uint4(0u, 0u, 0u, 0u);
            if (gn < N_NODES) v = ((const uint4*)g_hf)[gn * 16 + chunk * 8 + qq];
            *(uint4*)&sA[row * 72 + qq * 8] = v;
        }
        __syncthreads();
#pragma unroll
        for (int ks = 0; ks < 4; ks++) {
            int k0 = ks * 16;
            unsigned bl[4][2], brg[4][2];
#pragma unroll
            for (int nt = 0; nt < 4; nt++) {
                unsigned aL = smem_u32(&sB[(nt * 8 + br) * 264 + chunk * 64 + k0 + bc]);
                LDMATRIX_X2(bl[nt][0], bl[nt][1], aL);
                unsigned aR = smem_u32(&sB[(nt * 8 + br) * 264 + 128 + chunk * 64 + k0 + bc]);
                LDMATRIX_X2(brg[nt][0], brg[nt][1], aR);
            }
#pragma unroll
            for (int mt = 0; mt < 2; mt++) {
                unsigned a0, a1, a2, a3;
                unsigned addrA = smem_u32(&sA[(warp * 32 + mt * 16 + ar) * 72 + k0 + ac]);
                LDMATRIX_X4(a0, a1, a2, a3, addrA);
#pragma unroll
                for (int nt = 0; nt < 4; nt++) {
                    MMA16816(dp[mt * 4 + nt], a0, a1, a2, a3, bl[nt][0], bl[nt][1]);
                    MMA16816(dr[mt * 4 + nt], a0, a1, a2, a3, brg[nt][0], brg[nt][1]);
                }
            }
        }
    }

    int g = lane >> 2, tg = lane & 3;
#pragma unroll
    for (int mt = 0; mt < 2; mt++) {
        int nA = node0 + warp * 32 + mt * 16 + g;
        int nB = nA + 8;
#pragma unroll
        for (int nt = 0; nt < 4; nt++) {
            int col = nt * 8 + tg * 2;
            float bx = b2[col], by = b2[col + 1];
            float* pp = dp[mt * 4 + nt];
            float* rr = dr[mt * 4 + nt];
            if (nA < N_NODES) {
                __half2 h = __floats2half2_rn(pp[0], pp[1]);
                *(__half2*)&g_pf[nA * 32 + col] = h;
                float2 o = make_float2(rr[0] + bx, rr[1] + by);
                *(float2*)&out[nA * 32 + col] = o;
            }
            if (nB < N_NODES) {
                __half2 h = __floats2half2_rn(pp[2], pp[3]);
                *(__half2*)&g_pf[nB * 32 + col] = h;
                float2 o = make_float2(rr[2] + bx, rr[3] + by);
                *(float2*)&out[nB * 32 + col] = o;
            }
        }
    }
}

// ---------------- agg2p_add: out += mean_agg(p), in-place ------------------
__global__ void agg2p_add_kernel(float* __restrict__ out) {
    int node = blockIdx.x * 8 + (threadIdx.x >> 5);
    if (node >= N_NODES) return;
    int lane = threadIdx.x & 31;
    int q = lane >> 3, p = lane & 7;
    int b = g_off[node], e = g_off[node + 1];
    const uint2* p8 = (const uint2*)g_pf;
    float4 acc = make_float4(0.f, 0.f, 0.f, 0.f);
    for (int i = b + q; i < e; i += 4) {
        int s = g_col[i];
        uint2 raw = p8[s * 8 + p];
        __half2 h0 = *(__half2*)&raw.x;
        __half2 h1 = *(__half2*)&raw.y;
        float2 f0 = __half22float2(h0), f1 = __half22float2(h1);
        acc.x += f0.x; acc.y += f0.y; acc.z += f1.x; acc.w += f1.y;
    }
#pragma unroll
    for (int off = 8; off <= 16; off <<= 1) {
        acc.x += __shfl_xor_sync(0xffffffffu, acc.x, off);
        acc.y += __shfl_xor_sync(0xffffffffu, acc.y, off);
        acc.z += __shfl_xor_sync(0xffffffffu, acc.z, off);
        acc.w += __shfl_xor_sync(0xffffffffu, acc.w, off);
    }
    if (lane < 8) {
        float sc = g_inv[node];
        float4 cur = *(float4*)&out[node * 32 + p * 4];
        cur.x += acc.x * sc; cur.y += acc.y * sc;
        cur.z += acc.z * sc; cur.w += acc.w * sc;
        *(float4*)&out[node * 32 + p * 4] = cur;
    }
}

// ---------------- launch ---------------------------------------------------
extern "C" void kernel_launch(void* const* d_in, const int* in_sizes, int n_in,
                              void* d_out, int out_size) {
    const float* x   = (const float*)d_in[0];
    const void*  ei  = d_in[1];
    const float* W1l = (const float*)d_in[2];
    const float* W1r = (const float*)d_in[3];
    const float* b1  = (const float*)d_in[4];
    const float* W2l = (const float*)d_in[5];
    const float* W2r = (const float*)d_in[6];
    const float* b2  = (const float*)d_in[7];
    float* out = (float*)d_out;

    const int TB = 256;
    int nb_e4 = (N_EDGES / 4 + TB - 1) / TB;          // 1563

    prep_kernel<<<PB_TOT, TB>>>(x, W1l, W1r, W2l, W2r, ei);  // copy + rank-hist
    scan_fused_kernel<<<N_SBLK, SCAN_B>>>();
    scatter_kernel<<<nb_e4, TB>>>(ei);                        // atomic-free

    agg1_kernel<<<(N_NODES + 7) / 8, TB>>>();
    gemm1_mma<<<(N_NODES + 63) / 64, 128>>>(b1);
    gemm_pr_mma<<<(N_NODES + 127) / 128, 128>>>(b2, out);
    agg2p_add_kernel<<<(N_NODES + 7) / 8, TB>>>(out);
}